// round 2
// baseline (speedup 1.0000x reference)
#include <cuda_runtime.h>
#include <cstdint>

// ============================================================================
// CausalAttention: out = softmax(mask(Q K^T)/sqrt(d)) V,  Q/K/V = x @ W{q,k,v}
// B=4, S=4096, D=1024.  Strategy:
//   1) tf32x3-split mma.sync GEMM (fp32-accurate) for QKV projections
//   2) same GEMM (B-transposed, causal block skip) for scores
//   3) causal row softmax in-place (+ zero-fill up to diagonal block edge)
//   4) same GEMM (causal K-limit) for P @ V
// Scratch lives in static __device__ arrays (no allocations).
// ============================================================================

#define BM 128
#define BN 128
#define BK 32

static constexpr int Bb = 4;
static constexpr int S  = 4096;
static constexpr int D  = 1024;

static __device__ float g_q[(size_t)Bb * S * D];        // 64 MB
static __device__ float g_k[(size_t)Bb * S * D];        // 64 MB
static __device__ float g_v[(size_t)Bb * S * D];        // 64 MB
static __device__ float g_s[(size_t)Bb * S * S];        // 256 MB

// ---------------------------------------------------------------------------
// tf32 split:  x = hi + lo, both exactly representable in tf32.
// ---------------------------------------------------------------------------
__device__ __forceinline__ void tf32_split(float x, uint32_t& hi, uint32_t& lo) {
    uint32_t h;
    asm("cvt.rna.tf32.f32 %0, %1;" : "=r"(h) : "f"(x));
    float r = x - __uint_as_float(h);
    uint32_t l;
    asm("cvt.rna.tf32.f32 %0, %1;" : "=r"(l) : "f"(r));
    hi = h; lo = l;
}

__device__ __forceinline__ void mma_tf32(float (&d)[4], const uint32_t (&a)[4],
                                         const uint32_t (&b)[2]) {
    asm volatile(
        "mma.sync.aligned.m16n8k8.row.col.f32.tf32.tf32.f32 "
        "{%0,%1,%2,%3}, {%4,%5,%6,%7}, {%8,%9}, {%0,%1,%2,%3};"
        : "+f"(d[0]), "+f"(d[1]), "+f"(d[2]), "+f"(d[3])
        : "r"(a[0]), "r"(a[1]), "r"(a[2]), "r"(a[3]), "r"(b[0]), "r"(b[1]));
}

// ---------------------------------------------------------------------------
// Generic tiled GEMM, C = A * op(B), fp32 in/out, tf32x3 internally.
//   A: row-major M x K, leading dim lda
//   B: if !BT: row-major K x N (ldb); if BT: row-major N x K (ldb) -> use B^T
//   C: row-major M x N (ldc = N)
//   CAUSAL: skip blocks strictly above the diagonal (M==N, square tiles)
//   KLIM:   limit K loop to min(K, (block_row+1)*BM)  (for P@V causal)
// Batched over blockIdx.z with element strides sA/sB/sC.
// Requires M%128==0, N%128==0, K%32==0 (holds for all call sites).
// ---------------------------------------------------------------------------
template<bool BT, bool CAUSAL, bool KLIM>
__global__ void __launch_bounds__(256, 1)
gemm_tf32x3(const float* __restrict__ A, const float* __restrict__ Bm,
            float* __restrict__ C, int M, int N, int K, int lda, int ldb,
            long long sA, long long sB, long long sC)
{
    const int bm = blockIdx.y;
    const int bn = blockIdx.x;
    if (CAUSAL && bn > bm) return;   // block fully above diagonal

    A  += (long long)blockIdx.z * sA;
    Bm += (long long)blockIdx.z * sB;
    C  += (long long)blockIdx.z * sC;

    const int kEnd = KLIM ? min(K, (bm + 1) * BM) : K;

    __shared__ float As[BM][BK + 4];    // stride 36: conflict-free frag reads
    __shared__ float Bs[BK][BN + 8];    // stride 136: conflict-free frag reads

    const int tid  = threadIdx.x;
    const int wid  = tid >> 5;
    const int wm   = wid & 3;           // 4 warps along M
    const int wn   = wid >> 2;          // 2 warps along N
    const int lane = tid & 31;
    const int g    = lane >> 2;         // group id (row within 8)
    const int c    = lane & 3;          // thread-in-group (col within 4)

    // global load mappings
    const int at_row = tid >> 3;            // 0..31
    const int at_col = (tid & 7) * 4;       // 0..28
    const int bn_col = (tid & 31) * 4;      // 0..124   (!BT)
    const int bn_row = tid >> 5;            // 0..7     (!BT)
    const int bt_k   = (tid & 7) * 4;       // 0..28    (BT)
    const int bt_n   = tid >> 3;            // 0..31    (BT)

    float acc[2][8][4];
    #pragma unroll
    for (int mi = 0; mi < 2; mi++)
        #pragma unroll
        for (int ni = 0; ni < 8; ni++)
            #pragma unroll
            for (int q = 0; q < 4; q++) acc[mi][ni][q] = 0.f;

    for (int k0 = 0; k0 < kEnd; k0 += BK) {
        // ---- stage A tile: [BM][BK]
        #pragma unroll
        for (int rr = 0; rr < BM; rr += 32) {
            float4 vv = *(const float4*)(A + (long long)(bm * BM + at_row + rr) * lda
                                           + k0 + at_col);
            *(float4*)&As[at_row + rr][at_col] = vv;
        }
        // ---- stage B tile: Bs[k][n]
        if (!BT) {
            #pragma unroll
            for (int kk = 0; kk < BK; kk += 8) {
                float4 vv = *(const float4*)(Bm + (long long)(k0 + bn_row + kk) * ldb
                                               + bn * BN + bn_col);
                *(float4*)&Bs[bn_row + kk][bn_col] = vv;
            }
        } else {
            #pragma unroll
            for (int nn = 0; nn < BN; nn += 32) {
                float4 vv = *(const float4*)(Bm + (long long)(bn * BN + bt_n + nn) * ldb
                                               + k0 + bt_k);
                Bs[bt_k + 0][bt_n + nn] = vv.x;
                Bs[bt_k + 1][bt_n + nn] = vv.y;
                Bs[bt_k + 2][bt_n + nn] = vv.z;
                Bs[bt_k + 3][bt_n + nn] = vv.w;
            }
        }
        __syncthreads();

        // ---- compute: 4 k-steps of 8
        #pragma unroll
        for (int kt = 0; kt < 4; kt++) {
            const int k = kt * 8;
            uint32_t Ah[2][4], Al[2][4];
            #pragma unroll
            for (int mi = 0; mi < 2; mi++) {
                const int r = wm * 32 + mi * 16 + g;
                tf32_split(As[r][k + c],         Ah[mi][0], Al[mi][0]);
                tf32_split(As[r + 8][k + c],     Ah[mi][1], Al[mi][1]);
                tf32_split(As[r][k + c + 4],     Ah[mi][2], Al[mi][2]);
                tf32_split(As[r + 8][k + c + 4], Ah[mi][3], Al[mi][3]);
            }
            uint32_t Bh[8][2], Bl[8][2];
            #pragma unroll
            for (int ni = 0; ni < 8; ni++) {
                const int col = wn * 64 + ni * 8 + g;
                tf32_split(Bs[k + c][col],     Bh[ni][0], Bl[ni][0]);
                tf32_split(Bs[k + c + 4][col], Bh[ni][1], Bl[ni][1]);
            }
            #pragma unroll
            for (int mi = 0; mi < 2; mi++)
                #pragma unroll
                for (int ni = 0; ni < 8; ni++) {
                    mma_tf32(acc[mi][ni], Ah[mi], Bh[ni]);
                    mma_tf32(acc[mi][ni], Al[mi], Bh[ni]);
                    mma_tf32(acc[mi][ni], Ah[mi], Bl[ni]);
                }
        }
        __syncthreads();
    }

    // ---- epilogue
    #pragma unroll
    for (int mi = 0; mi < 2; mi++) {
        const int r0 = bm * BM + wm * 32 + mi * 16 + g;
        #pragma unroll
        for (int ni = 0; ni < 8; ni++) {
            const int cc = bn * BN + wn * 64 + ni * 8 + c * 2;
            float2 v0 = make_float2(acc[mi][ni][0], acc[mi][ni][1]);
            float2 v1 = make_float2(acc[mi][ni][2], acc[mi][ni][3]);
            *(float2*)(C + (long long)r0 * N + cc)       = v0;
            *(float2*)(C + (long long)(r0 + 8) * N + cc) = v1;
        }
    }
}

// ---------------------------------------------------------------------------
// Causal softmax over rows of scores, in place. Row i of batch b has i+1
// valid entries; entries (i, blockEnd) are zero-filled so the P@V GEMM can
// read whole diagonal blocks.
// ---------------------------------------------------------------------------
__global__ void __launch_bounds__(256)
softmax_causal(float* __restrict__ sc)
{
    const int r = blockIdx.x;
    const int b = r >> 12;
    const int i = r & (S - 1);
    float* row = sc + ((long long)b * S * S) + ((long long)i * S);
    const int n = i + 1;
    const int tid  = threadIdx.x;
    const int wid  = tid >> 5;
    const int lane = tid & 31;
    const float scale = 0.03125f;   // 1/sqrt(1024)

    __shared__ float sh[8];

    // pass 1: max (of raw scores; scale after, scale > 0)
    float m = -1e30f;
    for (int j = tid; j < n; j += 256) m = fmaxf(m, row[j]);
    #pragma unroll
    for (int o = 16; o > 0; o >>= 1) m = fmaxf(m, __shfl_xor_sync(0xffffffffu, m, o));
    if (lane == 0) sh[wid] = m;
    __syncthreads();
    m = sh[0];
    #pragma unroll
    for (int t = 1; t < 8; t++) m = fmaxf(m, sh[t]);
    const float ml = m * scale;
    __syncthreads();

    // pass 2: exp + sum, write unnormalized
    float s = 0.f;
    for (int j = tid; j < n; j += 256) {
        float e = __expf(row[j] * scale - ml);
        row[j] = e;
        s += e;
    }
    #pragma unroll
    for (int o = 16; o > 0; o >>= 1) s += __shfl_xor_sync(0xffffffffu, s, o);
    if (lane == 0) sh[wid] = s;
    __syncthreads();
    s = sh[0];
    #pragma unroll
    for (int t = 1; t < 8; t++) s += sh[t];
    const float inv = 1.0f / s;

    // pass 3: normalize
    for (int j = tid; j < n; j += 256) row[j] *= inv;

    // zero-fill to the edge of this row's diagonal 128-block
    const int end = ((i >> 7) + 1) << 7;
    for (int j = n + tid; j < end; j += 256) row[j] = 0.f;
}

// ---------------------------------------------------------------------------
extern "C" void kernel_launch(void* const* d_in, const int* in_sizes, int n_in,
                              void* d_out, int out_size)
{
    const float* x  = (const float*)d_in[0];
    const float* Wq = (const float*)d_in[1];
    const float* Wk = (const float*)d_in[2];
    const float* Wv = (const float*)d_in[3];
    float* out = (float*)d_out;

    // Resolve scratch addresses once (no driver calls on replay/capture).
    static float* q  = nullptr;
    static float* k  = nullptr;
    static float* v  = nullptr;
    static float* sc = nullptr;
    if (q == nullptr) {
        cudaGetSymbolAddress((void**)&q,  g_q);
        cudaGetSymbolAddress((void**)&k,  g_k);
        cudaGetSymbolAddress((void**)&v,  g_v);
        cudaGetSymbolAddress((void**)&sc, g_s);
    }

    const dim3 blk(256);
    const long long sQKV = (long long)S * D;     // per-batch stride of Q/K/V
    const long long sSS  = (long long)S * S;     // per-batch stride of scores

    // 1) QKV projections: [B*S, D] = x @ W
    gemm_tf32x3<false, false, false><<<dim3(D / BN, (Bb * S) / BM, 1), blk>>>(
        x, Wq, q, Bb * S, D, D, D, D, 0, 0, 0);
    gemm_tf32x3<false, false, false><<<dim3(D / BN, (Bb * S) / BM, 1), blk>>>(
        x, Wk, k, Bb * S, D, D, D, D, 0, 0, 0);
    gemm_tf32x3<false, false, false><<<dim3(D / BN, (Bb * S) / BM, 1), blk>>>(
        x, Wv, v, Bb * S, D, D, D, D, 0, 0, 0);

    // 2) scores = Q K^T (causal lower blocks only)
    gemm_tf32x3<true, true, false><<<dim3(S / BN, S / BM, Bb), blk>>>(
        q, k, sc, S, S, D, D, D, sQKV, sQKV, sSS);

    // 3) softmax (causal, in place)
    softmax_causal<<<Bb * S, 256>>>(sc);

    // 4) out = P @ V  (K loop limited to diagonal block)
    gemm_tf32x3<false, false, true><<<dim3(D / BN, S / BM, Bb), blk>>>(
        sc, v, out, S, D, S, S, D, sSS, sQKV, sQKV);
}

// round 3
// speedup vs baseline: 1.3667x; 1.3667x over previous
#include <cuda_runtime.h>
#include <cstdint>

// ============================================================================
// CausalAttention, B=4, S=4096, D=1024, fp32 in/out.
//   GEMMs run tf32x3-split mma.sync with hi/lo tiles PRE-SPLIT in smem,
//   double-buffered stages, register prefetch, one sync per 32-K chunk.
//   K is transposed once so every GEMM stages B with coalesced, conflict-free
//   stores. Softmax is 2-pass online. Scratch = static __device__ arrays.
// ============================================================================

#define BM 128
#define BN 128
#define BK 32

static constexpr int Bb = 4;
static constexpr int S  = 4096;
static constexpr int D  = 1024;

// per-stage smem layout (words): Ah[4096] Al[4096] Bh[4352] Bl[4352]
static constexpr int A_WORDS   = BM * BK;          // 4096 (stride 32, XOR swizzle)
static constexpr int B_STRIDE  = BN + 8;           // 136
static constexpr int B_WORDS   = BK * B_STRIDE;    // 4352
static constexpr int STAGE_W   = 2 * A_WORDS + 2 * B_WORDS;   // 16896
static constexpr int SMEM_BYTES = 2 * STAGE_W * 4;            // 135168

static __device__ float g_q [(size_t)Bb * S * D];
static __device__ float g_k [(size_t)Bb * S * D];
static __device__ float g_kt[(size_t)Bb * D * S];
static __device__ float g_v [(size_t)Bb * S * D];
static __device__ float g_s [(size_t)Bb * S * S];

// ---------------------------------------------------------------------------
__device__ __forceinline__ void tf32_split(float x, uint32_t& hi, uint32_t& lo) {
    uint32_t h;
    asm("cvt.rna.tf32.f32 %0, %1;" : "=r"(h) : "f"(x));
    float r = x - __uint_as_float(h);
    uint32_t l;
    asm("cvt.rna.tf32.f32 %0, %1;" : "=r"(l) : "f"(r));
    hi = h; lo = l;
}

__device__ __forceinline__ void mma_tf32(float (&d)[4], const uint32_t (&a)[4],
                                         const uint32_t (&b)[2]) {
    asm volatile(
        "mma.sync.aligned.m16n8k8.row.col.f32.tf32.tf32.f32 "
        "{%0,%1,%2,%3}, {%4,%5,%6,%7}, {%8,%9}, {%0,%1,%2,%3};"
        : "+f"(d[0]), "+f"(d[1]), "+f"(d[2]), "+f"(d[3])
        : "r"(a[0]), "r"(a[1]), "r"(a[2]), "r"(a[3]), "r"(b[0]), "r"(b[1]));
}

__device__ __forceinline__ void cvt_store4(uint32_t* hi, uint32_t* lo, int widx,
                                           float4 v) {
    uint4 h, l;
    tf32_split(v.x, h.x, l.x);
    tf32_split(v.y, h.y, l.y);
    tf32_split(v.z, h.z, l.z);
    tf32_split(v.w, h.w, l.w);
    *(uint4*)(hi + widx) = h;
    *(uint4*)(lo + widx) = l;
}

// ---------------------------------------------------------------------------
// C = A * B, A row-major MxK (lda), B row-major KxN (ldb), C row-major MxN.
// tf32x3 internally (drop lo*lo). Batched over blockIdx.z.
// CAUSAL: skip blocks above diagonal. KLIM: K limited to (bm+1)*BM.
// ---------------------------------------------------------------------------
template<bool CAUSAL, bool KLIM>
__global__ void __launch_bounds__(256, 1)
gemm_tf32x3(const float* __restrict__ A, const float* __restrict__ Bm,
            float* __restrict__ C, int M, int N, int K, int lda, int ldb,
            long long sA, long long sB, long long sC)
{
    const int bm = blockIdx.y;
    const int bn = blockIdx.x;
    if (CAUSAL && bn > bm) return;

    A  += (long long)blockIdx.z * sA;
    Bm += (long long)blockIdx.z * sB;
    C  += (long long)blockIdx.z * sC;

    const int kEnd = KLIM ? min(K, (bm + 1) * BM) : K;

    extern __shared__ uint32_t sm[];

    const int tid  = threadIdx.x;
    const int wid  = tid >> 5;
    const int wm   = wid & 3;
    const int wn   = wid >> 2;
    const int lane = tid & 31;
    const int g    = lane >> 2;
    const int c    = lane & 3;

    // staging maps
    const int at_row = tid >> 3;                 // 0..31
    const int at_col = (tid & 7) * 4;            // 0,4,..,28
    const int a_sw   = at_col ^ ((at_row & 7) << 2);
    const int bs_row = tid >> 5;                 // 0..7
    const int bs_col = (tid & 31) * 4;           // 0..124

    const float* Aptr = A + (long long)(bm * BM + at_row) * lda + at_col;
    const float* Bptr = Bm + (long long)bs_row * ldb + bn * BN + bs_col;

    float4 pa[4], pb[4];
    #pragma unroll
    for (int r = 0; r < 4; r++)
        pa[r] = *(const float4*)(Aptr + (long long)(r * 32) * lda);
    #pragma unroll
    for (int r = 0; r < 4; r++)
        pb[r] = *(const float4*)(Bptr + (long long)(r * 8) * ldb);

    // stage 0 store
    {
        uint32_t* Ah = sm;
        uint32_t* Al = sm + A_WORDS;
        uint32_t* Bh = sm + 2 * A_WORDS;
        uint32_t* Bl = Bh + B_WORDS;
        #pragma unroll
        for (int r = 0; r < 4; r++)
            cvt_store4(Ah, Al, (at_row + r * 32) * BK + a_sw, pa[r]);
        #pragma unroll
        for (int r = 0; r < 4; r++)
            cvt_store4(Bh, Bl, (bs_row + r * 8) * B_STRIDE + bs_col, pb[r]);
    }
    __syncthreads();

    float acc[2][8][4];
    #pragma unroll
    for (int mi = 0; mi < 2; mi++)
        #pragma unroll
        for (int ni = 0; ni < 8; ni++)
            #pragma unroll
            for (int q = 0; q < 4; q++) acc[mi][ni][q] = 0.f;

    int st = 0;
    for (int k0 = 0; k0 < kEnd; k0 += BK) {
        const bool has_next = (k0 + BK) < kEnd;
        if (has_next) {
            #pragma unroll
            for (int r = 0; r < 4; r++)
                pa[r] = *(const float4*)(Aptr + (long long)(r * 32) * lda + (k0 + BK));
            #pragma unroll
            for (int r = 0; r < 4; r++)
                pb[r] = *(const float4*)(Bptr + (long long)(k0 + BK + r * 8) * ldb);
        }

        const uint32_t* Ah = sm + st * STAGE_W;
        const uint32_t* Al = Ah + A_WORDS;
        const uint32_t* Bh = Ah + 2 * A_WORDS;
        const uint32_t* Bl = Bh + B_WORDS;

        #pragma unroll
        for (int kt = 0; kt < 4; kt++) {
            const int x0 = (kt * 8 + c)     ^ (g << 2);   // swizzled A col
            const int x1 = (kt * 8 + c + 4) ^ (g << 2);
            uint32_t ah[2][4], al[2][4];
            #pragma unroll
            for (int mi = 0; mi < 2; mi++) {
                const int r0 = (wm * 32 + mi * 16 + g) * BK;
                const int r1 = r0 + 8 * BK;
                ah[mi][0] = Ah[r0 + x0];  al[mi][0] = Al[r0 + x0];
                ah[mi][1] = Ah[r1 + x0];  al[mi][1] = Al[r1 + x0];
                ah[mi][2] = Ah[r0 + x1];  al[mi][2] = Al[r0 + x1];
                ah[mi][3] = Ah[r1 + x1];  al[mi][3] = Al[r1 + x1];
            }
            const int br0 = (kt * 8 + c) * B_STRIDE;
            const int br1 = (kt * 8 + c + 4) * B_STRIDE;
            #pragma unroll
            for (int ni = 0; ni < 8; ni++) {
                const int col = wn * 64 + ni * 8 + g;
                uint32_t bh[2], bl[2];
                bh[0] = Bh[br0 + col];  bh[1] = Bh[br1 + col];
                bl[0] = Bl[br0 + col];  bl[1] = Bl[br1 + col];
                #pragma unroll
                for (int mi = 0; mi < 2; mi++) {
                    mma_tf32(acc[mi][ni], ah[mi], bh);
                    mma_tf32(acc[mi][ni], al[mi], bh);
                    mma_tf32(acc[mi][ni], ah[mi], bl);
                }
            }
        }

        if (has_next) {
            uint32_t* nAh = sm + (st ^ 1) * STAGE_W;
            uint32_t* nAl = nAh + A_WORDS;
            uint32_t* nBh = nAh + 2 * A_WORDS;
            uint32_t* nBl = nBh + B_WORDS;
            #pragma unroll
            for (int r = 0; r < 4; r++)
                cvt_store4(nAh, nAl, (at_row + r * 32) * BK + a_sw, pa[r]);
            #pragma unroll
            for (int r = 0; r < 4; r++)
                cvt_store4(nBh, nBl, (bs_row + r * 8) * B_STRIDE + bs_col, pb[r]);
        }
        __syncthreads();
        st ^= 1;
    }

    // epilogue
    #pragma unroll
    for (int mi = 0; mi < 2; mi++) {
        const int r0 = bm * BM + wm * 32 + mi * 16 + g;
        #pragma unroll
        for (int ni = 0; ni < 8; ni++) {
            const int cc = bn * BN + wn * 64 + ni * 8 + c * 2;
            float2 v0 = make_float2(acc[mi][ni][0], acc[mi][ni][1]);
            float2 v1 = make_float2(acc[mi][ni][2], acc[mi][ni][3]);
            *(float2*)(C + (long long)r0 * N + cc)       = v0;
            *(float2*)(C + (long long)(r0 + 8) * N + cc) = v1;
        }
    }
}

// ---------------------------------------------------------------------------
// K transpose: [B][S][D] -> [B][D][S], tiled 32x32.
// ---------------------------------------------------------------------------
__global__ void __launch_bounds__(256)
transpose_k(const float* __restrict__ src, float* __restrict__ dst)
{
    __shared__ float t[32][33];
    const int s0 = blockIdx.x << 5;
    const int d0 = blockIdx.y << 5;
    const int tx = threadIdx.x & 31;
    const int ty = threadIdx.x >> 5;          // 0..7
    const float* sp = src + (size_t)blockIdx.z * S * D;
    float*       dp = dst + (size_t)blockIdx.z * D * S;
    #pragma unroll
    for (int i = 0; i < 32; i += 8)
        t[ty + i][tx] = sp[(size_t)(s0 + ty + i) * D + d0 + tx];
    __syncthreads();
    #pragma unroll
    for (int i = 0; i < 32; i += 8)
        dp[(size_t)(d0 + ty + i) * S + s0 + tx] = t[tx][ty + i];
}

// ---------------------------------------------------------------------------
// Causal softmax, 2-pass online. Zero-fills to the 128-block edge.
// ---------------------------------------------------------------------------
__global__ void __launch_bounds__(256)
softmax_causal(float* __restrict__ sc)
{
    const int r = blockIdx.x;
    const int b = r >> 12;
    const int i = r & (S - 1);
    float* row = sc + ((long long)b * S * S) + ((long long)i * S);
    const int n = i + 1;
    const int tid  = threadIdx.x;
    const int wid  = tid >> 5;
    const int lane = tid & 31;
    const float scale = 0.03125f;   // 1/sqrt(1024)

    __shared__ float shm[8], shs[8];

    // pass 1: online (max, sum)
    float m = -3.0e38f, s = 0.f;
    for (int j = tid; j < n; j += 256) {
        float v = row[j];
        if (v <= m) {
            s += __expf((v - m) * scale);
        } else {
            s = s * __expf((m - v) * scale) + 1.f;
            m = v;
        }
    }
    #pragma unroll
    for (int o = 16; o > 0; o >>= 1) {
        float mo = __shfl_xor_sync(0xffffffffu, m, o);
        float so = __shfl_xor_sync(0xffffffffu, s, o);
        float M  = fmaxf(m, mo);
        s = s * __expf((m - M) * scale) + so * __expf((mo - M) * scale);
        m = M;
    }
    if (lane == 0) { shm[wid] = m; shs[wid] = s; }
    __syncthreads();
    float M = shm[0], Sm = shs[0];
    #pragma unroll
    for (int t = 1; t < 8; t++) {
        float mo = shm[t], so = shs[t];
        float Mx = fmaxf(M, mo);
        Sm = Sm * __expf((M - Mx) * scale) + so * __expf((mo - Mx) * scale);
        M = Mx;
    }
    const float inv = 1.0f / Sm;

    // pass 2: write normalized probabilities
    for (int j = tid; j < n; j += 256)
        row[j] = __expf((row[j] - M) * scale) * inv;

    // zero-fill to the edge of this row's diagonal 128-block
    const int end = ((i >> 7) + 1) << 7;
    for (int j = n + tid; j < end; j += 256) row[j] = 0.f;
}

// ---------------------------------------------------------------------------
extern "C" void kernel_launch(void* const* d_in, const int* in_sizes, int n_in,
                              void* d_out, int out_size)
{
    const float* x  = (const float*)d_in[0];
    const float* Wq = (const float*)d_in[1];
    const float* Wk = (const float*)d_in[2];
    const float* Wv = (const float*)d_in[3];
    float* out = (float*)d_out;

    static float *q = nullptr, *k = nullptr, *kt = nullptr, *v = nullptr,
                 *sc = nullptr;
    static bool init = false;
    if (!init) {
        cudaGetSymbolAddress((void**)&q,  g_q);
        cudaGetSymbolAddress((void**)&k,  g_k);
        cudaGetSymbolAddress((void**)&kt, g_kt);
        cudaGetSymbolAddress((void**)&v,  g_v);
        cudaGetSymbolAddress((void**)&sc, g_s);
        cudaFuncSetAttribute(gemm_tf32x3<false, false>,
                             cudaFuncAttributeMaxDynamicSharedMemorySize, SMEM_BYTES);
        cudaFuncSetAttribute(gemm_tf32x3<true, false>,
                             cudaFuncAttributeMaxDynamicSharedMemorySize, SMEM_BYTES);
        cudaFuncSetAttribute(gemm_tf32x3<false, true>,
                             cudaFuncAttributeMaxDynamicSharedMemorySize, SMEM_BYTES);
        init = true;
    }

    const dim3 blk(256);
    const long long sQKV = (long long)S * D;
    const long long sTK  = (long long)D * S;
    const long long sSS  = (long long)S * S;

    // 1) QKV projections
    gemm_tf32x3<false, false><<<dim3(D / BN, (Bb * S) / BM, 1), blk, SMEM_BYTES>>>(
        x, Wq, q, Bb * S, D, D, D, D, 0, 0, 0);
    gemm_tf32x3<false, false><<<dim3(D / BN, (Bb * S) / BM, 1), blk, SMEM_BYTES>>>(
        x, Wk, k, Bb * S, D, D, D, D, 0, 0, 0);
    gemm_tf32x3<false, false><<<dim3(D / BN, (Bb * S) / BM, 1), blk, SMEM_BYTES>>>(
        x, Wv, v, Bb * S, D, D, D, D, 0, 0, 0);

    // 2) K -> K^T
    transpose_k<<<dim3(S / 32, D / 32, Bb), blk>>>(k, kt);

    // 3) scores = Q K^T  (B = K^T, ldb = S)
    gemm_tf32x3<true, false><<<dim3(S / BN, S / BM, Bb), blk, SMEM_BYTES>>>(
        q, kt, sc, S, S, D, D, S, sQKV, sTK, sSS);

    // 4) softmax
    softmax_causal<<<Bb * S, 256>>>(sc);

    // 5) out = P @ V
    gemm_tf32x3<false, true><<<dim3(D / BN, S / BM, Bb), blk, SMEM_BYTES>>>(
        sc, v, out, S, D, S, S, D, sSS, sQKV, sQKV);
}